// round 13
// baseline (speedup 1.0000x reference)
#include <cuda_runtime.h>
#include <math_constants.h>

#define NN 100000
#define NE 1600000
#define ET (NE + NN)      // edges incl. self loops = 1700000
#define F  64
#define NFI 128
#define NLAY 4
#define SCAN_B 1024
#define NSB ((NN + SCAN_B - 1) / SCAN_B)   // 98
#define DBINS 128

// ---------------- device scratch (static globals; no runtime alloc) ----------
__device__ float d_x[NN * F];      // node state
__device__ float d_g[NN * F];      // per-layer linear output
__device__ float d_h[NN * F];      // running h accumulator
__device__ float d_e[ET];          // per-edge raw logits (sorted slot order)
__device__ int   d_deg[NN];        // zero-initialized at load; re-zeroed by k_scatter
__device__ int   d_off[NN + 1];
__device__ int   d_cur[NN];
__device__ int   d_bsum[NSB];
__device__ int   d_boff[NSB];
__device__ int   d_ssrc[ET];       // src node per sorted edge slot
__device__ int   d_seid[ET];       // original edge id per sorted slot
__device__ int   d_dhist[DBINS];   // degree histogram (zero-init; re-zeroed)
__device__ int   d_dcur2[DBINS];   // bin cursors
__device__ int   d_perm[NN];       // nodes sorted by degree
__device__ float d_sum[F];         // zero-initialized; re-zeroed by k_stats
__device__ float d_sumsq[F];
__device__ float d_scale[F];
__device__ float d_shift[F];

__device__ __forceinline__ float lrelu(float v, float s) { return v > 0.f ? v : s * v; }

// ---------------- histogram of dst (deg starts at 0) -------------------------
__global__ void k_hist(const int* __restrict__ ei) {
    int e = blockIdx.x * blockDim.x + threadIdx.x;
    if (e < NE) atomicAdd(&d_deg[ei[NE + e]], 1);
}

// ---------------- parallel scan, pass 1: per-block sums ----------------------
__global__ void k_scan1() {
    int i = blockIdx.x * SCAN_B + threadIdx.x;
    int v = (i < NN) ? (d_deg[i] + 1) : 0;   // +1 = self loop
    __shared__ int ws[32];
    int lane = threadIdx.x & 31, wid = threadIdx.x >> 5;
    #pragma unroll
    for (int o = 16; o > 0; o >>= 1) v += __shfl_xor_sync(0xFFFFFFFFu, v, o);
    if (lane == 0) ws[wid] = v;
    __syncthreads();
    if (wid == 0) {
        int s = ws[lane];
        #pragma unroll
        for (int o = 16; o > 0; o >>= 1) s += __shfl_xor_sync(0xFFFFFFFFu, s, o);
        if (lane == 0) d_bsum[blockIdx.x] = s;
    }
}

// ---------------- pass 2: single block scans the 98 block sums ---------------
__global__ void k_scan2() {
    int t = threadIdx.x;                      // 128 threads
    int v = (t < NSB) ? d_bsum[t] : 0;
    int lane = t & 31, wid = t >> 5;
    int x = v;
    #pragma unroll
    for (int o = 1; o < 32; o <<= 1) {
        int u = __shfl_up_sync(0xFFFFFFFFu, x, o);
        if (lane >= o) x += u;
    }
    __shared__ int wsum[4];
    if (lane == 31) wsum[wid] = x;
    __syncthreads();
    int add = 0;
    for (int k = 0; k < wid; k++) add += wsum[k];
    x += add;
    if (t < NSB) d_boff[t] = x - v;           // exclusive
    if (t == NSB - 1) d_off[NN] = x;
}

// ---------------- pass 3: per-block rescan + global offset -------------------
__global__ void k_scan3() {
    int b = blockIdx.x;
    int i = b * SCAN_B + threadIdx.x;
    int v = (i < NN) ? (d_deg[i] + 1) : 0;
    int lane = threadIdx.x & 31, wid = threadIdx.x >> 5;
    int x = v;
    #pragma unroll
    for (int o = 1; o < 32; o <<= 1) {
        int u = __shfl_up_sync(0xFFFFFFFFu, x, o);
        if (lane >= o) x += u;
    }
    __shared__ int ws[32];
    if (lane == 31) ws[wid] = x;
    __syncthreads();
    if (wid == 0) {
        int s = ws[lane];
        #pragma unroll
        for (int o = 1; o < 32; o <<= 1) {
            int u = __shfl_up_sync(0xFFFFFFFFu, s, o);
            if (lane >= o) s += u;
        }
        ws[lane] = s;
    }
    __syncthreads();
    int pre = (wid == 0) ? 0 : ws[wid - 1];
    int off = d_boff[b] + pre + x - v;        // exclusive within block
    if (i < NN) { d_off[i] = off; d_cur[i] = off; }
}

// ---------------- degree counting sort: histogram ----------------------------
__global__ void k_dhist() {
    int i = blockIdx.x * blockDim.x + threadIdx.x;
    if (i < NN) {
        int b = d_deg[i] + 1; if (b > DBINS - 1) b = DBINS - 1;
        atomicAdd(&d_dhist[b], 1);
    }
}

// ---------------- degree sort: scan bins (1 block, 128 thr); re-zero hist ----
__global__ void k_dscan() {
    int t = threadIdx.x;
    int v = d_dhist[t];
    int lane = t & 31, wid = t >> 5;
    int x = v;
    #pragma unroll
    for (int o = 1; o < 32; o <<= 1) {
        int u = __shfl_up_sync(0xFFFFFFFFu, x, o);
        if (lane >= o) x += u;
    }
    __shared__ int wsum[4];
    if (lane == 31) wsum[wid] = x;
    __syncthreads();
    int add = 0;
    for (int k = 0; k < wid; k++) add += wsum[k];
    x += add;
    d_dcur2[t] = x - v;          // exclusive bin offset
    d_dhist[t] = 0;              // ready for next replay
}

// ---------------- degree sort: scatter node ids ------------------------------
__global__ void k_dscatter() {
    int i = blockIdx.x * blockDim.x + threadIdx.x;
    if (i < NN) {
        int b = d_deg[i] + 1; if (b > DBINS - 1) b = DBINS - 1;
        int pos = atomicAdd(&d_dcur2[b], 1);
        d_perm[pos] = i;
    }
}

// ------ scatter edges into CSR slots; also re-zero deg for next replay -------
__global__ void k_scatter(const int* __restrict__ ei) {
    int idx = blockIdx.x * blockDim.x + threadIdx.x;
    if (idx < NN) d_deg[idx] = 0;
    if (idx >= ET) return;
    int s, d;
    if (idx < NE) { s = ei[idx]; d = ei[NE + idx]; }
    else          { s = idx - NE; d = s; }
    int p = atomicAdd(&d_cur[d], 1);
    d_ssrc[p] = s;
    d_seid[p] = idx;
}

// ---------------- encoder: x = lrelu(concat(xf, emb[id]) @ Win + bin) --------
__global__ void __launch_bounds__(256) k_enc(
        const float* __restrict__ xf, const int* __restrict__ ids,
        const float* __restrict__ emb, const float* __restrict__ w,
        const float* __restrict__ b) {
    __shared__ float Wsm[NFI * F];       // 32 KB, row-major [k][f]
    __shared__ float Xin[128 * 32];      // 16 KB chunk
    int tid = threadIdx.x;
    {
        const float4* wg = (const float4*)w;
        float4* ws = (float4*)Wsm;
        #pragma unroll
        for (int q = tid; q < NFI * F / 4; q += 256) ws[q] = wg[q];
    }
    int node0 = blockIdx.x * 128;
    int f4 = tid & 15;          // feature group (4 feats)
    int ng = tid >> 4;          // node group (8 nodes)
    float4 bb = ((const float4*)b)[f4];
    float4 acc[8];
    #pragma unroll
    for (int j = 0; j < 8; j++) acc[j] = bb;
    const float4* W4 = (const float4*)Wsm;

    #pragma unroll
    for (int c = 0; c < 4; c++) {
        __syncthreads();
        float4* xs4 = (float4*)Xin;
        #pragma unroll
        for (int q = tid; q < 128 * 8; q += 256) {
            int nl = q >> 3, c4 = q & 7;
            int node = node0 + nl;
            int gc4 = c * 8 + c4;
            float4 v = make_float4(0.f, 0.f, 0.f, 0.f);
            if (node < NN) {
                if (gc4 < 31) v = ((const float4*)(xf + (size_t)node * 124))[gc4];
                else          v = ((const float4*)emb)[ids[node]];
            }
            xs4[q] = v;
        }
        __syncthreads();
        const float4* X4 = (const float4*)(&Xin[ng * 8 * 32]);
        #pragma unroll
        for (int k4 = 0; k4 < 8; k4++) {
            int gk = c * 32 + k4 * 4;
            float4 w0 = W4[(gk + 0) * 16 + f4];
            float4 w1 = W4[(gk + 1) * 16 + f4];
            float4 w2 = W4[(gk + 2) * 16 + f4];
            float4 w3 = W4[(gk + 3) * 16 + f4];
            #pragma unroll
            for (int j = 0; j < 8; j++) {
                float4 xv = X4[j * 8 + k4];
                acc[j].x += xv.x * w0.x + xv.y * w1.x + xv.z * w2.x + xv.w * w3.x;
                acc[j].y += xv.x * w0.y + xv.y * w1.y + xv.z * w2.y + xv.w * w3.y;
                acc[j].z += xv.x * w0.z + xv.y * w1.z + xv.z * w2.z + xv.w * w3.z;
                acc[j].w += xv.x * w0.w + xv.y * w1.w + xv.z * w2.w + xv.w * w3.w;
            }
        }
    }
    #pragma unroll
    for (int j = 0; j < 8; j++) {
        int node = node0 + ng * 8 + j;
        if (node < NN) {
            float4 o;
            o.x = lrelu(acc[j].x, 0.01f);
            o.y = lrelu(acc[j].y, 0.01f);
            o.z = lrelu(acc[j].z, 0.01f);
            o.w = lrelu(acc[j].w, 0.01f);
            ((float4*)d_x)[node * 16 + f4] = o;
        }
    }
}

// ---------------- per-layer linear: g = norm(x) @ W + b ----------------------
__global__ void __launch_bounds__(256) k_lin(const float* __restrict__ w,
                                             const float* __restrict__ b,
                                             int donorm, int hmode) {
    __shared__ float Wsm[F * F];         // 16 KB, row-major [k][f]
    __shared__ float Xin[128 * F];       // 32 KB
    int tid = threadIdx.x;
    {
        const float4* wg = (const float4*)w;
        float4* ws = (float4*)Wsm;
        #pragma unroll
        for (int q = tid; q < F * F / 4; q += 256) ws[q] = wg[q];
    }
    int node0 = blockIdx.x * 128;
    {
        float4* xs = (float4*)Xin;
        const float4* xg = (const float4*)d_x;
        float4* hg = (float4*)d_h;
        for (int q = tid; q < 128 * 16; q += 256) {
            int node = node0 + (q >> 4);
            float4 xv = make_float4(0.f, 0.f, 0.f, 0.f);
            if (node < NN) {
                xv = xg[node0 * 16 + q];
                if (donorm) {
                    int fi = q & 15;
                    float4 sc = ((const float4*)d_scale)[fi];
                    float4 sh = ((const float4*)d_shift)[fi];
                    xv.x = lrelu(xv.x * sc.x + sh.x, 0.01f);
                    xv.y = lrelu(xv.y * sc.y + sh.y, 0.01f);
                    xv.z = lrelu(xv.z * sc.z + sh.z, 0.01f);
                    xv.w = lrelu(xv.w * sc.w + sh.w, 0.01f);
                    float4 hv;
                    if (hmode == 1) {
                        hv = make_float4(0.5f * xv.x, 0.5f * xv.y,
                                         0.5f * xv.z, 0.5f * xv.w);
                    } else {
                        hv = hg[node0 * 16 + q];
                        hv.x += 0.5f * xv.x; hv.y += 0.5f * xv.y;
                        hv.z += 0.5f * xv.z; hv.w += 0.5f * xv.w;
                    }
                    hg[node0 * 16 + q] = hv;
                }
            }
            xs[q] = xv;
        }
    }
    __syncthreads();
    int f4 = tid & 15;
    int ng = tid >> 4;
    const float4* W4 = (const float4*)Wsm;
    const float4* X4 = (const float4*)(&Xin[ng * 8 * F]);
    float4 bb = ((const float4*)b)[f4];
    float4 acc[8];
    #pragma unroll
    for (int j = 0; j < 8; j++) acc[j] = bb;
    #pragma unroll 2
    for (int k4 = 0; k4 < F / 4; k4++) {
        float4 w0 = W4[(4 * k4 + 0) * 16 + f4];
        float4 w1 = W4[(4 * k4 + 1) * 16 + f4];
        float4 w2 = W4[(4 * k4 + 2) * 16 + f4];
        float4 w3 = W4[(4 * k4 + 3) * 16 + f4];
        #pragma unroll
        for (int j = 0; j < 8; j++) {
            float4 xv = X4[j * (F / 4) + k4];
            acc[j].x += xv.x * w0.x + xv.y * w1.x + xv.z * w2.x + xv.w * w3.x;
            acc[j].y += xv.x * w0.y + xv.y * w1.y + xv.z * w2.y + xv.w * w3.y;
            acc[j].z += xv.x * w0.z + xv.y * w1.z + xv.z * w2.z + xv.w * w3.z;
            acc[j].w += xv.x * w0.w + xv.y * w1.w + xv.z * w2.w + xv.w * w3.w;
        }
    }
    #pragma unroll
    for (int j = 0; j < 8; j++) {
        int node = node0 + ng * 8 + j;
        if (node < NN)
            ((float4*)d_g)[node * 16 + f4] = acc[j];
    }
}

// 8-feature logit contribution for one lane
#define DOT8(va, vb)                                                          \
    (lrelu((va).x + gda.x, 0.2f) * aa.x + lrelu((va).y + gda.y, 0.2f) * aa.y  \
   + lrelu((va).z + gda.z, 0.2f) * aa.z + lrelu((va).w + gda.w, 0.2f) * aa.w  \
   + lrelu((vb).x + gdb.x, 0.2f) * ab.x + lrelu((vb).y + gdb.y, 0.2f) * ab.y  \
   + lrelu((vb).z + gdb.z, 0.2f) * ab.z + lrelu((vb).w + gdb.w, 0.2f) * ab.w)

// branchless online-softmax update (8-feature acc), single MUFU
#define OUPD8(t, va, vb)                                            \
    {                                                               \
        bool gt = (t) > m;                                          \
        float es = __expf(-fabsf((t) - m));                         \
        float cs = gt ? es : 1.f;                                   \
        float ee = gt ? 1.f : es;                                   \
        ssum = ssum * cs + ee;                                      \
        accA.x = accA.x * cs + ee * (va).x;                         \
        accA.y = accA.y * cs + ee * (va).y;                         \
        accA.z = accA.z * cs + ee * (va).z;                         \
        accA.w = accA.w * cs + ee * (va).w;                         \
        accB.x = accB.x * cs + ee * (vb).x;                         \
        accB.y = accB.y * cs + ee * (vb).y;                         \
        accB.z = accB.z * cs + ee * (vb).z;                         \
        accB.w = accB.w * cs + ee * (vb).w;                         \
        m = fmaxf(m, (t));                                          \
    }

// ---------------- fused GATv2 edge phase + GraphNorm partial reduction --------
// One warp per dst node (degree-sorted via d_perm); QUARTER-WARP per edge,
// lane holds 8 features. 8 edges per iteration via 2 interleaved shfl chains.
// Epilogue: block-level sum/sumsq reduction of the 8 output nodes.
__global__ void __launch_bounds__(256) k_gat(const float* __restrict__ att,
                                             const float* __restrict__ cb,
                                             float* __restrict__ xs_out) {
    __shared__ float sm_s[8 * F];   // [warp][feature] x sums
    __shared__ float sm_q[8 * F];   // [warp][feature] x^2 sums
    int lane = threadIdx.x & 31;
    int wl = threadIdx.x >> 5;      // warp index in block
    // grid is exactly NN/8 blocks (NN % 8 == 0): every warp owns a valid node.
    int w = d_perm[(blockIdx.x * blockDim.x + threadIdx.x) >> 5];
    int beg = d_off[w], end = d_off[w + 1];
    int qt = lane >> 3;         // quarter: 0..3
    int r  = lane & 7;          // float4 slot within half-row

    const float4* g4 = (const float4*)d_g;
    float4 aa  = __ldg((const float4*)att + r);
    float4 ab  = __ldg((const float4*)att + 8 + r);
    float4 gda = __ldg(g4 + w * 16 + r);
    float4 gdb = __ldg(g4 + w * 16 + 8 + r);

    float m = -1e30f, ssum = 0.f;
    float4 accA = make_float4(0.f, 0.f, 0.f, 0.f);
    float4 accB = make_float4(0.f, 0.f, 0.f, 0.f);

    int p = beg;
    for (; p + 7 < end; p += 8) {
        int s0 = __ldg(d_ssrc + p + qt);          // chain0: edges p..p+3
        int s1 = __ldg(d_ssrc + p + 4 + qt);      // chain1: edges p+4..p+7
        float4 va0 = __ldg(g4 + s0 * 16 + r);
        float4 vb0 = __ldg(g4 + s0 * 16 + 8 + r);
        float4 va1 = __ldg(g4 + s1 * 16 + r);
        float4 vb1 = __ldg(g4 + s1 * 16 + 8 + r);
        float t0 = DOT8(va0, vb0);
        float t1 = DOT8(va1, vb1);
        #pragma unroll
        for (int o = 4; o > 0; o >>= 1) {         // reduce within 8-lane quarter
            t0 += __shfl_xor_sync(0xFFFFFFFFu, t0, o);
            t1 += __shfl_xor_sync(0xFFFFFFFFu, t1, o);
        }
        if (r == 0) { d_e[p + qt] = t0; d_e[p + 4 + qt] = t1; }
        OUPD8(t0, va0, vb0);
        OUPD8(t1, va1, vb1);
    }
    // remainder: clamped groups of 4 edges (phantoms neutralized with -inf)
    for (; p < end; p += 4) {
        int idx = p + qt;
        bool valid = idx < end;
        if (!valid) idx = end - 1;
        int s0 = __ldg(d_ssrc + idx);
        float4 va = __ldg(g4 + s0 * 16 + r);
        float4 vb = __ldg(g4 + s0 * 16 + 8 + r);
        float t0 = DOT8(va, vb);
        #pragma unroll
        for (int o = 4; o > 0; o >>= 1)
            t0 += __shfl_xor_sync(0xFFFFFFFFu, t0, o);
        if (!valid) t0 = -CUDART_INF_F;
        if (r == 0 && valid) d_e[idx] = t0;
        OUPD8(t0, va, vb);
    }

    // merge the 4 quarter-states
    #pragma unroll
    for (int off = 16; off >= 8; off >>= 1) {
        float mO = __shfl_down_sync(0xFFFFFFFFu, m, off);
        float sO = __shfl_down_sync(0xFFFFFFFFu, ssum, off);
        float4 aO, bO;
        aO.x = __shfl_down_sync(0xFFFFFFFFu, accA.x, off);
        aO.y = __shfl_down_sync(0xFFFFFFFFu, accA.y, off);
        aO.z = __shfl_down_sync(0xFFFFFFFFu, accA.z, off);
        aO.w = __shfl_down_sync(0xFFFFFFFFu, accA.w, off);
        bO.x = __shfl_down_sync(0xFFFFFFFFu, accB.x, off);
        bO.y = __shfl_down_sync(0xFFFFFFFFu, accB.y, off);
        bO.z = __shfl_down_sync(0xFFFFFFFFu, accB.z, off);
        bO.w = __shfl_down_sync(0xFFFFFFFFu, accB.w, off);
        float M2 = fmaxf(m, mO);
        float cA = __expf(m - M2), cB = __expf(mO - M2);
        ssum  = ssum * cA + sO * cB;
        accA.x = accA.x * cA + aO.x * cB;
        accA.y = accA.y * cA + aO.y * cB;
        accA.z = accA.z * cA + aO.z * cB;
        accA.w = accA.w * cA + aO.w * cB;
        accB.x = accB.x * cA + bO.x * cB;
        accB.y = accB.y * cA + bO.y * cB;
        accB.z = accB.z * cA + bO.z * cB;
        accB.w = accB.w * cA + bO.w * cB;
        m = M2;
    }
    float inv = 1.f / ssum;
    float M = __shfl_sync(0xFFFFFFFFu, m, lane & 7);
    inv     = __shfl_sync(0xFFFFFFFFu, inv, lane & 7);

    // alpha pass: scalar logit -> alpha, lanes stride over edges
    for (int e = beg + lane; e < end; e += 32)
        xs_out[d_seid[e]] = __expf(d_e[e] - M) * inv;

    if (lane < 8) {
        float4 cba = __ldg((const float4*)cb + r);
        float4 cbb = __ldg((const float4*)cb + 8 + r);
        float4 xa, xb;
        xa.x = accA.x * inv + cba.x;
        xa.y = accA.y * inv + cba.y;
        xa.z = accA.z * inv + cba.z;
        xa.w = accA.w * inv + cba.w;
        xb.x = accB.x * inv + cbb.x;
        xb.y = accB.y * inv + cbb.y;
        xb.z = accB.z * inv + cbb.z;
        xb.w = accB.w * inv + cbb.w;
        ((float4*)d_x)[w * 16 + r]     = xa;
        ((float4*)d_x)[w * 16 + 8 + r] = xb;
        // stash for block GraphNorm reduction
        float* ss = &sm_s[wl * F];
        float* sq = &sm_q[wl * F];
        ss[4 * r + 0] = xa.x;  sq[4 * r + 0] = xa.x * xa.x;
        ss[4 * r + 1] = xa.y;  sq[4 * r + 1] = xa.y * xa.y;
        ss[4 * r + 2] = xa.z;  sq[4 * r + 2] = xa.z * xa.z;
        ss[4 * r + 3] = xa.w;  sq[4 * r + 3] = xa.w * xa.w;
        ss[32 + 4 * r + 0] = xb.x;  sq[32 + 4 * r + 0] = xb.x * xb.x;
        ss[32 + 4 * r + 1] = xb.y;  sq[32 + 4 * r + 1] = xb.y * xb.y;
        ss[32 + 4 * r + 2] = xb.z;  sq[32 + 4 * r + 2] = xb.z * xb.z;
        ss[32 + 4 * r + 3] = xb.w;  sq[32 + 4 * r + 3] = xb.w * xb.w;
    }
    __syncthreads();
    if (threadIdx.x < F) {
        int f = threadIdx.x;
        float s = 0.f, s2 = 0.f;
        #pragma unroll
        for (int k = 0; k < 8; k++) {
            s  += sm_s[k * F + f];
            s2 += sm_q[k * F + f];
        }
        atomicAdd(&d_sum[f], s);
        atomicAdd(&d_sumsq[f], s2);
    }
}

// stats: compute scale/shift, then zero accumulators for next layer/replay
__global__ void k_stats(const float* __restrict__ gw, const float* __restrict__ gb,
                        const float* __restrict__ gms) {
    int f = threadIdx.x;
    if (f >= F) return;
    const float invn = 1.f / (float)NN;
    float mean = d_sum[f] * invn;
    float ex2  = d_sumsq[f] * invn;
    float mm   = mean * gms[f];
    float var  = ex2 - 2.f * mm * mean + mm * mm;
    float inv  = rsqrtf(var + 1e-5f);
    float sc   = inv * gw[f];
    d_scale[f] = sc;
    d_shift[f] = gb[f] - mm * sc;
    d_sum[f] = 0.f;
    d_sumsq[f] = 0.f;
}

// final norm: apply last layer's GraphNorm, write outputs x and h
__global__ void k_norm_final(float* __restrict__ outx, float* __restrict__ outh) {
    int total = NN * F;
    for (int i = blockIdx.x * blockDim.x + threadIdx.x; i < total;
         i += gridDim.x * blockDim.x) {
        int f = i & 63;
        float v = d_x[i] * d_scale[f] + d_shift[f];
        v = lrelu(v, 0.01f);
        outx[i] = v;
        outh[i] = d_h[i] + 0.5f * v;
    }
}

// ---------------- launch ------------------------------------------------------
extern "C" void kernel_launch(void* const* d_in, const int* in_sizes, int n_in,
                              void* d_out, int out_size) {
    const float* x_feat   = (const float*)d_in[0];
    const int*   node_ids = (const int*)  d_in[1];
    const int*   edge_idx = (const int*)  d_in[2];
    const float* emb      = (const float*)d_in[3];
    const float* w_in     = (const float*)d_in[4];
    const float* b_in     = (const float*)d_in[5];
    const float* lin_w    = (const float*)d_in[6];
    const float* lin_b    = (const float*)d_in[7];
    const float* att      = (const float*)d_in[8];
    const float* conv_b   = (const float*)d_in[9];
    const float* gn_w     = (const float*)d_in[10];
    const float* gn_b     = (const float*)d_in[11];
    const float* gn_ms    = (const float*)d_in[12];
    float* out = (float*)d_out;

    k_enc<<<(NN + 127) / 128, 256>>>(x_feat, node_ids, emb, w_in, b_in);
    k_hist<<<(NE + 255) / 256, 256>>>(edge_idx);
    k_scan1<<<NSB, SCAN_B>>>();
    k_lin<<<(NN + 127) / 128, 256>>>(lin_w, lin_b, 0, 0);   // layer 0, no norm
    k_scan2<<<1, 128>>>();
    k_scan3<<<NSB, SCAN_B>>>();
    // degree counting sort (uses d_deg before k_scatter zeroes it)
    k_dhist<<<(NN + 255) / 256, 256>>>();
    k_dscan<<<1, DBINS>>>();
    k_dscatter<<<(NN + 255) / 256, 256>>>();
    k_scatter<<<(ET + 255) / 256, 256>>>(edge_idx);

    for (int l = 0; l < NLAY; l++) {
        if (l > 0)   // layers 1-3: fused norm of previous layer + h accumulate
            k_lin<<<(NN + 127) / 128, 256>>>(lin_w + l * F * F, lin_b + l * F,
                                             1, l == 1 ? 1 : 2);
        k_gat<<<NN / 8, 256>>>(att + l * F, conv_b + l * F,
                               out + 2 * NN * F + (size_t)l * ET);
        k_stats<<<1, 64>>>(gn_w + l * F, gn_b + l * F, gn_ms + l * F);
    }

    k_norm_final<<<1024, 256>>>(out, out + NN * F);

    (void)in_sizes; (void)n_in; (void)out_size;
}

// round 14
// speedup vs baseline: 1.0989x; 1.0989x over previous
#include <cuda_runtime.h>
#include <math_constants.h>

#define NN 100000
#define NE 1600000
#define ET (NE + NN)      // edges incl. self loops = 1700000
#define F  64
#define NFI 128
#define NLAY 4
#define SCAN_B 1024
#define NSB ((NN + SCAN_B - 1) / SCAN_B)   // 98

// ---------------- device scratch (static globals; no runtime alloc) ----------
__device__ float d_x[NN * F];      // node state
__device__ float d_g[NN * F];      // per-layer linear output
__device__ float d_h[NN * F];      // running h accumulator
__device__ float d_e[ET];          // per-edge raw logits (sorted slot order)
__device__ int   d_deg[NN];        // zero-initialized at load; re-zeroed by k_scatter
__device__ int   d_off[NN + 1];
__device__ int   d_cur[NN];
__device__ int   d_bsum[NSB];
__device__ int   d_boff[NSB];
__device__ int   d_ssrc[ET];       // src node per sorted edge slot
__device__ int   d_seid[ET];       // original edge id per sorted slot
__device__ float d_sum[F];         // zero-initialized; re-zeroed by k_stats
__device__ float d_sumsq[F];
__device__ float d_scale[F];
__device__ float d_shift[F];

__device__ __forceinline__ float lrelu(float v, float s) { return v > 0.f ? v : s * v; }

// ---------------- histogram of dst (deg starts at 0) -------------------------
__global__ void k_hist(const int* __restrict__ ei) {
    int e = blockIdx.x * blockDim.x + threadIdx.x;
    if (e < NE) atomicAdd(&d_deg[ei[NE + e]], 1);
}

// ---------------- parallel scan, pass 1: per-block sums ----------------------
__global__ void k_scan1() {
    int i = blockIdx.x * SCAN_B + threadIdx.x;
    int v = (i < NN) ? (d_deg[i] + 1) : 0;   // +1 = self loop
    __shared__ int ws[32];
    int lane = threadIdx.x & 31, wid = threadIdx.x >> 5;
    #pragma unroll
    for (int o = 16; o > 0; o >>= 1) v += __shfl_xor_sync(0xFFFFFFFFu, v, o);
    if (lane == 0) ws[wid] = v;
    __syncthreads();
    if (wid == 0) {
        int s = ws[lane];
        #pragma unroll
        for (int o = 16; o > 0; o >>= 1) s += __shfl_xor_sync(0xFFFFFFFFu, s, o);
        if (lane == 0) d_bsum[blockIdx.x] = s;
    }
}

// ---------------- pass 2: single block scans the 98 block sums ---------------
__global__ void k_scan2() {
    int t = threadIdx.x;                      // 128 threads
    int v = (t < NSB) ? d_bsum[t] : 0;
    int lane = t & 31, wid = t >> 5;
    int x = v;
    #pragma unroll
    for (int o = 1; o < 32; o <<= 1) {
        int u = __shfl_up_sync(0xFFFFFFFFu, x, o);
        if (lane >= o) x += u;
    }
    __shared__ int wsum[4];
    if (lane == 31) wsum[wid] = x;
    __syncthreads();
    int add = 0;
    for (int k = 0; k < wid; k++) add += wsum[k];
    x += add;
    if (t < NSB) d_boff[t] = x - v;           // exclusive
    if (t == NSB - 1) d_off[NN] = x;
}

// ---------------- pass 3: per-block rescan + global offset -------------------
__global__ void k_scan3() {
    int b = blockIdx.x;
    int i = b * SCAN_B + threadIdx.x;
    int v = (i < NN) ? (d_deg[i] + 1) : 0;
    int lane = threadIdx.x & 31, wid = threadIdx.x >> 5;
    int x = v;
    #pragma unroll
    for (int o = 1; o < 32; o <<= 1) {
        int u = __shfl_up_sync(0xFFFFFFFFu, x, o);
        if (lane >= o) x += u;
    }
    __shared__ int ws[32];
    if (lane == 31) ws[wid] = x;
    __syncthreads();
    if (wid == 0) {
        int s = ws[lane];
        #pragma unroll
        for (int o = 1; o < 32; o <<= 1) {
            int u = __shfl_up_sync(0xFFFFFFFFu, s, o);
            if (lane >= o) s += u;
        }
        ws[lane] = s;
    }
    __syncthreads();
    int pre = (wid == 0) ? 0 : ws[wid - 1];
    int off = d_boff[b] + pre + x - v;        // exclusive within block
    if (i < NN) { d_off[i] = off; d_cur[i] = off; }
}

// ------ scatter edges into CSR slots; also re-zero deg for next replay -------
__global__ void k_scatter(const int* __restrict__ ei) {
    int idx = blockIdx.x * blockDim.x + threadIdx.x;
    if (idx < NN) d_deg[idx] = 0;
    if (idx >= ET) return;
    int s, d;
    if (idx < NE) { s = ei[idx]; d = ei[NE + idx]; }
    else          { s = idx - NE; d = s; }
    int p = atomicAdd(&d_cur[d], 1);
    d_ssrc[p] = s;
    d_seid[p] = idx;
}

// ---------------- encoder: x = lrelu(concat(xf, emb[id]) @ Win + bin) --------
__global__ void __launch_bounds__(256, 3) k_enc(
        const float* __restrict__ xf, const int* __restrict__ ids,
        const float* __restrict__ emb, const float* __restrict__ w,
        const float* __restrict__ b) {
    __shared__ float Wsm[NFI * F];       // 32 KB, row-major [k][f]
    __shared__ float Xin[128 * 32];      // 16 KB chunk
    int tid = threadIdx.x;
    {
        const float4* wg = (const float4*)w;
        float4* ws = (float4*)Wsm;
        #pragma unroll
        for (int q = tid; q < NFI * F / 4; q += 256) ws[q] = wg[q];
    }
    int node0 = blockIdx.x * 128;
    int f4 = tid & 15;          // feature group (4 feats)
    int ng = tid >> 4;          // node group (8 nodes)
    float4 bb = ((const float4*)b)[f4];
    float4 acc[8];
    #pragma unroll
    for (int j = 0; j < 8; j++) acc[j] = bb;
    const float4* W4 = (const float4*)Wsm;

    #pragma unroll
    for (int c = 0; c < 4; c++) {
        __syncthreads();
        float4* xs4 = (float4*)Xin;
        #pragma unroll
        for (int q = tid; q < 128 * 8; q += 256) {
            int nl = q >> 3, c4 = q & 7;
            int node = node0 + nl;
            int gc4 = c * 8 + c4;
            float4 v = make_float4(0.f, 0.f, 0.f, 0.f);
            if (node < NN) {
                if (gc4 < 31) v = ((const float4*)(xf + (size_t)node * 124))[gc4];
                else          v = ((const float4*)emb)[ids[node]];
            }
            xs4[q] = v;
        }
        __syncthreads();
        const float4* X4 = (const float4*)(&Xin[ng * 8 * 32]);
        #pragma unroll
        for (int k4 = 0; k4 < 8; k4++) {
            int gk = c * 32 + k4 * 4;
            float4 w0 = W4[(gk + 0) * 16 + f4];
            float4 w1 = W4[(gk + 1) * 16 + f4];
            float4 w2 = W4[(gk + 2) * 16 + f4];
            float4 w3 = W4[(gk + 3) * 16 + f4];
            #pragma unroll
            for (int j = 0; j < 8; j++) {
                float4 xv = X4[j * 8 + k4];
                acc[j].x += xv.x * w0.x + xv.y * w1.x + xv.z * w2.x + xv.w * w3.x;
                acc[j].y += xv.x * w0.y + xv.y * w1.y + xv.z * w2.y + xv.w * w3.y;
                acc[j].z += xv.x * w0.z + xv.y * w1.z + xv.z * w2.z + xv.w * w3.z;
                acc[j].w += xv.x * w0.w + xv.y * w1.w + xv.z * w2.w + xv.w * w3.w;
            }
        }
    }
    #pragma unroll
    for (int j = 0; j < 8; j++) {
        int node = node0 + ng * 8 + j;
        if (node < NN) {
            float4 o;
            o.x = lrelu(acc[j].x, 0.01f);
            o.y = lrelu(acc[j].y, 0.01f);
            o.z = lrelu(acc[j].z, 0.01f);
            o.w = lrelu(acc[j].w, 0.01f);
            ((float4*)d_x)[node * 16 + f4] = o;
        }
    }
}

// ---------------- per-layer linear: g = norm(x) @ W + b ----------------------
__global__ void __launch_bounds__(256, 3) k_lin(const float* __restrict__ w,
                                                const float* __restrict__ b,
                                                int donorm, int hmode) {
    __shared__ float Wsm[F * F];         // 16 KB, row-major [k][f]
    __shared__ float Xin[128 * F];       // 32 KB
    int tid = threadIdx.x;
    {
        const float4* wg = (const float4*)w;
        float4* ws = (float4*)Wsm;
        #pragma unroll
        for (int q = tid; q < F * F / 4; q += 256) ws[q] = wg[q];
    }
    int node0 = blockIdx.x * 128;
    {
        float4* xs = (float4*)Xin;
        const float4* xg = (const float4*)d_x;
        float4* hg = (float4*)d_h;
        for (int q = tid; q < 128 * 16; q += 256) {
            int node = node0 + (q >> 4);
            float4 xv = make_float4(0.f, 0.f, 0.f, 0.f);
            if (node < NN) {
                xv = xg[node0 * 16 + q];
                if (donorm) {
                    int fi = q & 15;
                    float4 sc = ((const float4*)d_scale)[fi];
                    float4 sh = ((const float4*)d_shift)[fi];
                    xv.x = lrelu(xv.x * sc.x + sh.x, 0.01f);
                    xv.y = lrelu(xv.y * sc.y + sh.y, 0.01f);
                    xv.z = lrelu(xv.z * sc.z + sh.z, 0.01f);
                    xv.w = lrelu(xv.w * sc.w + sh.w, 0.01f);
                    float4 hv;
                    if (hmode == 1) {
                        hv = make_float4(0.5f * xv.x, 0.5f * xv.y,
                                         0.5f * xv.z, 0.5f * xv.w);
                    } else {
                        hv = hg[node0 * 16 + q];
                        hv.x += 0.5f * xv.x; hv.y += 0.5f * xv.y;
                        hv.z += 0.5f * xv.z; hv.w += 0.5f * xv.w;
                    }
                    hg[node0 * 16 + q] = hv;
                }
            }
            xs[q] = xv;
        }
    }
    __syncthreads();
    int f4 = tid & 15;
    int ng = tid >> 4;
    const float4* W4 = (const float4*)Wsm;
    const float4* X4 = (const float4*)(&Xin[ng * 8 * F]);
    float4 bb = ((const float4*)b)[f4];
    float4 acc[8];
    #pragma unroll
    for (int j = 0; j < 8; j++) acc[j] = bb;
    #pragma unroll 2
    for (int k4 = 0; k4 < F / 4; k4++) {
        float4 w0 = W4[(4 * k4 + 0) * 16 + f4];
        float4 w1 = W4[(4 * k4 + 1) * 16 + f4];
        float4 w2 = W4[(4 * k4 + 2) * 16 + f4];
        float4 w3 = W4[(4 * k4 + 3) * 16 + f4];
        #pragma unroll
        for (int j = 0; j < 8; j++) {
            float4 xv = X4[j * (F / 4) + k4];
            acc[j].x += xv.x * w0.x + xv.y * w1.x + xv.z * w2.x + xv.w * w3.x;
            acc[j].y += xv.x * w0.y + xv.y * w1.y + xv.z * w2.y + xv.w * w3.y;
            acc[j].z += xv.x * w0.z + xv.y * w1.z + xv.z * w2.z + xv.w * w3.z;
            acc[j].w += xv.x * w0.w + xv.y * w1.w + xv.z * w2.w + xv.w * w3.w;
        }
    }
    #pragma unroll
    for (int j = 0; j < 8; j++) {
        int node = node0 + ng * 8 + j;
        if (node < NN)
            ((float4*)d_g)[node * 16 + f4] = acc[j];
    }
}

// 8-feature logit contribution for one lane
#define DOT8(va, vb)                                                          \
    (lrelu((va).x + gda.x, 0.2f) * aa.x + lrelu((va).y + gda.y, 0.2f) * aa.y  \
   + lrelu((va).z + gda.z, 0.2f) * aa.z + lrelu((va).w + gda.w, 0.2f) * aa.w  \
   + lrelu((vb).x + gdb.x, 0.2f) * ab.x + lrelu((vb).y + gdb.y, 0.2f) * ab.y  \
   + lrelu((vb).z + gdb.z, 0.2f) * ab.z + lrelu((vb).w + gdb.w, 0.2f) * ab.w)

// branchless online-softmax update (8-feature acc), single MUFU
#define OUPD8(t, va, vb)                                            \
    {                                                               \
        bool gt = (t) > m;                                          \
        float es = __expf(-fabsf((t) - m));                         \
        float cs = gt ? es : 1.f;                                   \
        float ee = gt ? 1.f : es;                                   \
        ssum = ssum * cs + ee;                                      \
        accA.x = accA.x * cs + ee * (va).x;                         \
        accA.y = accA.y * cs + ee * (va).y;                         \
        accA.z = accA.z * cs + ee * (va).z;                         \
        accA.w = accA.w * cs + ee * (va).w;                         \
        accB.x = accB.x * cs + ee * (vb).x;                         \
        accB.y = accB.y * cs + ee * (vb).y;                         \
        accB.z = accB.z * cs + ee * (vb).z;                         \
        accB.w = accB.w * cs + ee * (vb).w;                         \
        m = fmaxf(m, (t));                                          \
    }

// ---------------- fused GATv2 edge phase + GraphNorm partial reduction --------
// One warp per dst node; QUARTER-WARP (8 lanes) per edge, lane holds 8 features.
// 8 edges per iteration via 2 interleaved 3-level shfl chains.
// Epilogue: block-level sum/sumsq reduction of the 8 output nodes.
__global__ void __launch_bounds__(256) k_gat(const float* __restrict__ att,
                                             const float* __restrict__ cb,
                                             float* __restrict__ xs_out) {
    __shared__ float sm_s[8 * F];   // [warp][feature] x sums
    __shared__ float sm_q[8 * F];   // [warp][feature] x^2 sums
    int w = (blockIdx.x * blockDim.x + threadIdx.x) >> 5;
    int lane = threadIdx.x & 31;
    int wl = threadIdx.x >> 5;      // warp index in block
    // grid is exactly NN/8 blocks (NN % 8 == 0): every warp owns a valid node.
    int beg = d_off[w], end = d_off[w + 1];
    int qt = lane >> 3;         // quarter: 0..3
    int r  = lane & 7;          // float4 slot within half-row

    const float4* g4 = (const float4*)d_g;
    float4 aa  = __ldg((const float4*)att + r);
    float4 ab  = __ldg((const float4*)att + 8 + r);
    float4 gda = __ldg(g4 + w * 16 + r);
    float4 gdb = __ldg(g4 + w * 16 + 8 + r);

    float m = -1e30f, ssum = 0.f;
    float4 accA = make_float4(0.f, 0.f, 0.f, 0.f);
    float4 accB = make_float4(0.f, 0.f, 0.f, 0.f);

    int p = beg;
    for (; p + 7 < end; p += 8) {
        int s0 = __ldg(d_ssrc + p + qt);          // chain0: edges p..p+3
        int s1 = __ldg(d_ssrc + p + 4 + qt);      // chain1: edges p+4..p+7
        float4 va0 = __ldg(g4 + s0 * 16 + r);
        float4 vb0 = __ldg(g4 + s0 * 16 + 8 + r);
        float4 va1 = __ldg(g4 + s1 * 16 + r);
        float4 vb1 = __ldg(g4 + s1 * 16 + 8 + r);
        float t0 = DOT8(va0, vb0);
        float t1 = DOT8(va1, vb1);
        #pragma unroll
        for (int o = 4; o > 0; o >>= 1) {         // reduce within 8-lane quarter
            t0 += __shfl_xor_sync(0xFFFFFFFFu, t0, o);
            t1 += __shfl_xor_sync(0xFFFFFFFFu, t1, o);
        }
        if (r == 0) { d_e[p + qt] = t0; d_e[p + 4 + qt] = t1; }
        OUPD8(t0, va0, vb0);
        OUPD8(t1, va1, vb1);
    }
    // remainder: clamped groups of 4 edges (phantoms neutralized with -inf)
    for (; p < end; p += 4) {
        int idx = p + qt;
        bool valid = idx < end;
        if (!valid) idx = end - 1;
        int s0 = __ldg(d_ssrc + idx);
        float4 va = __ldg(g4 + s0 * 16 + r);
        float4 vb = __ldg(g4 + s0 * 16 + 8 + r);
        float t0 = DOT8(va, vb);
        #pragma unroll
        for (int o = 4; o > 0; o >>= 1)
            t0 += __shfl_xor_sync(0xFFFFFFFFu, t0, o);
        if (!valid) t0 = -CUDART_INF_F;
        if (r == 0 && valid) d_e[idx] = t0;
        OUPD8(t0, va, vb);
    }

    // merge the 4 quarter-states
    #pragma unroll
    for (int off = 16; off >= 8; off >>= 1) {
        float mO = __shfl_down_sync(0xFFFFFFFFu, m, off);
        float sO = __shfl_down_sync(0xFFFFFFFFu, ssum, off);
        float4 aO, bO;
        aO.x = __shfl_down_sync(0xFFFFFFFFu, accA.x, off);
        aO.y = __shfl_down_sync(0xFFFFFFFFu, accA.y, off);
        aO.z = __shfl_down_sync(0xFFFFFFFFu, accA.z, off);
        aO.w = __shfl_down_sync(0xFFFFFFFFu, accA.w, off);
        bO.x = __shfl_down_sync(0xFFFFFFFFu, accB.x, off);
        bO.y = __shfl_down_sync(0xFFFFFFFFu, accB.y, off);
        bO.z = __shfl_down_sync(0xFFFFFFFFu, accB.z, off);
        bO.w = __shfl_down_sync(0xFFFFFFFFu, accB.w, off);
        float M2 = fmaxf(m, mO);
        float cA = __expf(m - M2), cB = __expf(mO - M2);
        ssum  = ssum * cA + sO * cB;
        accA.x = accA.x * cA + aO.x * cB;
        accA.y = accA.y * cA + aO.y * cB;
        accA.z = accA.z * cA + aO.z * cB;
        accA.w = accA.w * cA + aO.w * cB;
        accB.x = accB.x * cA + bO.x * cB;
        accB.y = accB.y * cA + bO.y * cB;
        accB.z = accB.z * cA + bO.z * cB;
        accB.w = accB.w * cA + bO.w * cB;
        m = M2;
    }
    float inv = 1.f / ssum;
    float M = __shfl_sync(0xFFFFFFFFu, m, lane & 7);
    inv     = __shfl_sync(0xFFFFFFFFu, inv, lane & 7);

    // alpha pass: scalar logit -> alpha, lanes stride over edges
    for (int e = beg + lane; e < end; e += 32)
        xs_out[d_seid[e]] = __expf(d_e[e] - M) * inv;

    if (lane < 8) {
        float4 cba = __ldg((const float4*)cb + r);
        float4 cbb = __ldg((const float4*)cb + 8 + r);
        float4 xa, xb;
        xa.x = accA.x * inv + cba.x;
        xa.y = accA.y * inv + cba.y;
        xa.z = accA.z * inv + cba.z;
        xa.w = accA.w * inv + cba.w;
        xb.x = accB.x * inv + cbb.x;
        xb.y = accB.y * inv + cbb.y;
        xb.z = accB.z * inv + cbb.z;
        xb.w = accB.w * inv + cbb.w;
        ((float4*)d_x)[w * 16 + r]     = xa;
        ((float4*)d_x)[w * 16 + 8 + r] = xb;
        // stash for block GraphNorm reduction
        float* ss = &sm_s[wl * F];
        float* sq = &sm_q[wl * F];
        ss[4 * r + 0] = xa.x;  sq[4 * r + 0] = xa.x * xa.x;
        ss[4 * r + 1] = xa.y;  sq[4 * r + 1] = xa.y * xa.y;
        ss[4 * r + 2] = xa.z;  sq[4 * r + 2] = xa.z * xa.z;
        ss[4 * r + 3] = xa.w;  sq[4 * r + 3] = xa.w * xa.w;
        ss[32 + 4 * r + 0] = xb.x;  sq[32 + 4 * r + 0] = xb.x * xb.x;
        ss[32 + 4 * r + 1] = xb.y;  sq[32 + 4 * r + 1] = xb.y * xb.y;
        ss[32 + 4 * r + 2] = xb.z;  sq[32 + 4 * r + 2] = xb.z * xb.z;
        ss[32 + 4 * r + 3] = xb.w;  sq[32 + 4 * r + 3] = xb.w * xb.w;
    }
    __syncthreads();
    if (threadIdx.x < F) {
        int f = threadIdx.x;
        float s = 0.f, s2 = 0.f;
        #pragma unroll
        for (int k = 0; k < 8; k++) {
            s  += sm_s[k * F + f];
            s2 += sm_q[k * F + f];
        }
        atomicAdd(&d_sum[f], s);
        atomicAdd(&d_sumsq[f], s2);
    }
}

// stats: compute scale/shift, then zero accumulators for next layer/replay
__global__ void k_stats(const float* __restrict__ gw, const float* __restrict__ gb,
                        const float* __restrict__ gms) {
    int f = threadIdx.x;
    if (f >= F) return;
    const float invn = 1.f / (float)NN;
    float mean = d_sum[f] * invn;
    float ex2  = d_sumsq[f] * invn;
    float mm   = mean * gms[f];
    float var  = ex2 - 2.f * mm * mean + mm * mm;
    float inv  = rsqrtf(var + 1e-5f);
    float sc   = inv * gw[f];
    d_scale[f] = sc;
    d_shift[f] = gb[f] - mm * sc;
    d_sum[f] = 0.f;
    d_sumsq[f] = 0.f;
}

// final norm: apply last layer's GraphNorm, write outputs x and h
__global__ void k_norm_final(float* __restrict__ outx, float* __restrict__ outh) {
    int total = NN * F;
    for (int i = blockIdx.x * blockDim.x + threadIdx.x; i < total;
         i += gridDim.x * blockDim.x) {
        int f = i & 63;
        float v = d_x[i] * d_scale[f] + d_shift[f];
        v = lrelu(v, 0.01f);
        outx[i] = v;
        outh[i] = d_h[i] + 0.5f * v;
    }
}

// ---------------- launch ------------------------------------------------------
extern "C" void kernel_launch(void* const* d_in, const int* in_sizes, int n_in,
                              void* d_out, int out_size) {
    const float* x_feat   = (const float*)d_in[0];
    const int*   node_ids = (const int*)  d_in[1];
    const int*   edge_idx = (const int*)  d_in[2];
    const float* emb      = (const float*)d_in[3];
    const float* w_in     = (const float*)d_in[4];
    const float* b_in     = (const float*)d_in[5];
    const float* lin_w    = (const float*)d_in[6];
    const float* lin_b    = (const float*)d_in[7];
    const float* att      = (const float*)d_in[8];
    const float* conv_b   = (const float*)d_in[9];
    const float* gn_w     = (const float*)d_in[10];
    const float* gn_b     = (const float*)d_in[11];
    const float* gn_ms    = (const float*)d_in[12];
    float* out = (float*)d_out;

    k_enc<<<(NN + 127) / 128, 256>>>(x_feat, node_ids, emb, w_in, b_in);
    k_hist<<<(NE + 255) / 256, 256>>>(edge_idx);
    k_scan1<<<NSB, SCAN_B>>>();
    k_lin<<<(NN + 127) / 128, 256>>>(lin_w, lin_b, 0, 0);   // layer 0, no norm
    k_scan2<<<1, 128>>>();
    k_scan3<<<NSB, SCAN_B>>>();
    k_scatter<<<(ET + 255) / 256, 256>>>(edge_idx);

    for (int l = 0; l < NLAY; l++) {
        if (l > 0)   // layers 1-3: fused norm of previous layer + h accumulate
            k_lin<<<(NN + 127) / 128, 256>>>(lin_w + l * F * F, lin_b + l * F,
                                             1, l == 1 ? 1 : 2);
        k_gat<<<NN / 8, 256>>>(att + l * F, conv_b + l * F,
                               out + 2 * NN * F + (size_t)l * ET);
        k_stats<<<1, 64>>>(gn_w + l * F, gn_b + l * F, gn_ms + l * F);
    }

    k_norm_final<<<1024, 256>>>(out, out + NN * F);

    (void)in_sizes; (void)n_in; (void)out_size;
}

// round 15
// speedup vs baseline: 1.1395x; 1.0370x over previous
#include <cuda_runtime.h>
#include <math_constants.h>

#define NN 100000
#define NE 1600000
#define ET (NE + NN)      // edges incl. self loops = 1700000
#define F  64
#define NFI 128
#define NLAY 4
#define SCAN_B 1024
#define NSB ((NN + SCAN_B - 1) / SCAN_B)   // 98

// ---------------- device scratch (static globals; no runtime alloc) ----------
__device__ float d_x[NN * F];      // node state
__device__ float d_g[NN * F];      // per-layer linear output
__device__ float d_h[NN * F];      // running h accumulator
__device__ float d_e[ET];          // per-edge raw logits (sorted slot order)
__device__ int   d_deg[NN];        // zero-initialized at load; re-zeroed by k_scatter
__device__ int   d_off[NN + 1];
__device__ int   d_cur[NN];
__device__ int   d_bsum[NSB];
__device__ int   d_boff[NSB];
__device__ int   d_ssrc[ET];       // src node per sorted edge slot
__device__ int   d_seid[ET];       // original edge id per sorted slot
__device__ float d_sum[F];         // zero-initialized; re-zeroed by k_stats
__device__ float d_sumsq[F];
__device__ float d_scale[F];
__device__ float d_shift[F];

__device__ __forceinline__ float lrelu(float v, float s) { return v > 0.f ? v : s * v; }

// ---------------- histogram of dst (deg starts at 0) -------------------------
__global__ void k_hist(const int* __restrict__ ei) {
    int e = blockIdx.x * blockDim.x + threadIdx.x;
    if (e < NE) atomicAdd(&d_deg[ei[NE + e]], 1);
}

// ---------------- parallel scan, pass 1: per-block sums ----------------------
__global__ void k_scan1() {
    int i = blockIdx.x * SCAN_B + threadIdx.x;
    int v = (i < NN) ? (d_deg[i] + 1) : 0;   // +1 = self loop
    __shared__ int ws[32];
    int lane = threadIdx.x & 31, wid = threadIdx.x >> 5;
    #pragma unroll
    for (int o = 16; o > 0; o >>= 1) v += __shfl_xor_sync(0xFFFFFFFFu, v, o);
    if (lane == 0) ws[wid] = v;
    __syncthreads();
    if (wid == 0) {
        int s = ws[lane];
        #pragma unroll
        for (int o = 16; o > 0; o >>= 1) s += __shfl_xor_sync(0xFFFFFFFFu, s, o);
        if (lane == 0) d_bsum[blockIdx.x] = s;
    }
}

// ---------------- pass 2: single block scans the 98 block sums ---------------
__global__ void k_scan2() {
    int t = threadIdx.x;                      // 128 threads
    int v = (t < NSB) ? d_bsum[t] : 0;
    int lane = t & 31, wid = t >> 5;
    int x = v;
    #pragma unroll
    for (int o = 1; o < 32; o <<= 1) {
        int u = __shfl_up_sync(0xFFFFFFFFu, x, o);
        if (lane >= o) x += u;
    }
    __shared__ int wsum[4];
    if (lane == 31) wsum[wid] = x;
    __syncthreads();
    int add = 0;
    for (int k = 0; k < wid; k++) add += wsum[k];
    x += add;
    if (t < NSB) d_boff[t] = x - v;           // exclusive
    if (t == NSB - 1) d_off[NN] = x;
}

// ---------------- pass 3: per-block rescan + global offset -------------------
__global__ void k_scan3() {
    int b = blockIdx.x;
    int i = b * SCAN_B + threadIdx.x;
    int v = (i < NN) ? (d_deg[i] + 1) : 0;
    int lane = threadIdx.x & 31, wid = threadIdx.x >> 5;
    int x = v;
    #pragma unroll
    for (int o = 1; o < 32; o <<= 1) {
        int u = __shfl_up_sync(0xFFFFFFFFu, x, o);
        if (lane >= o) x += u;
    }
    __shared__ int ws[32];
    if (lane == 31) ws[wid] = x;
    __syncthreads();
    if (wid == 0) {
        int s = ws[lane];
        #pragma unroll
        for (int o = 1; o < 32; o <<= 1) {
            int u = __shfl_up_sync(0xFFFFFFFFu, s, o);
            if (lane >= o) s += u;
        }
        ws[lane] = s;
    }
    __syncthreads();
    int pre = (wid == 0) ? 0 : ws[wid - 1];
    int off = d_boff[b] + pre + x - v;        // exclusive within block
    if (i < NN) { d_off[i] = off; d_cur[i] = off; }
}

// ------ scatter edges into CSR slots; also re-zero deg for next replay -------
__global__ void k_scatter(const int* __restrict__ ei) {
    int idx = blockIdx.x * blockDim.x + threadIdx.x;
    if (idx < NN) d_deg[idx] = 0;
    if (idx >= ET) return;
    int s, d;
    if (idx < NE) { s = ei[idx]; d = ei[NE + idx]; }
    else          { s = idx - NE; d = s; }
    int p = atomicAdd(&d_cur[d], 1);
    d_ssrc[p] = s;
    d_seid[p] = idx;
}

// ---------------- encoder: x = lrelu(concat(xf, emb[id]) @ Win + bin) --------
__global__ void __launch_bounds__(256, 3) k_enc(
        const float* __restrict__ xf, const int* __restrict__ ids,
        const float* __restrict__ emb, const float* __restrict__ w,
        const float* __restrict__ b) {
    __shared__ float Wsm[NFI * F];       // 32 KB, row-major [k][f]
    __shared__ float Xin[128 * 32];      // 16 KB chunk
    int tid = threadIdx.x;
    {
        const float4* wg = (const float4*)w;
        float4* ws = (float4*)Wsm;
        #pragma unroll
        for (int q = tid; q < NFI * F / 4; q += 256) ws[q] = wg[q];
    }
    int node0 = blockIdx.x * 128;
    int f4 = tid & 15;          // feature group (4 feats)
    int ng = tid >> 4;          // node group (8 nodes)
    float4 bb = ((const float4*)b)[f4];
    float4 acc[8];
    #pragma unroll
    for (int j = 0; j < 8; j++) acc[j] = bb;
    const float4* W4 = (const float4*)Wsm;

    #pragma unroll
    for (int c = 0; c < 4; c++) {
        __syncthreads();
        float4* xs4 = (float4*)Xin;
        #pragma unroll
        for (int q = tid; q < 128 * 8; q += 256) {
            int nl = q >> 3, c4 = q & 7;
            int node = node0 + nl;
            int gc4 = c * 8 + c4;
            float4 v = make_float4(0.f, 0.f, 0.f, 0.f);
            if (node < NN) {
                if (gc4 < 31) v = ((const float4*)(xf + (size_t)node * 124))[gc4];
                else          v = ((const float4*)emb)[ids[node]];
            }
            xs4[q] = v;
        }
        __syncthreads();
        const float4* X4 = (const float4*)(&Xin[ng * 8 * 32]);
        #pragma unroll
        for (int k4 = 0; k4 < 8; k4++) {
            int gk = c * 32 + k4 * 4;
            float4 w0 = W4[(gk + 0) * 16 + f4];
            float4 w1 = W4[(gk + 1) * 16 + f4];
            float4 w2 = W4[(gk + 2) * 16 + f4];
            float4 w3 = W4[(gk + 3) * 16 + f4];
            #pragma unroll
            for (int j = 0; j < 8; j++) {
                float4 xv = X4[j * 8 + k4];
                acc[j].x += xv.x * w0.x + xv.y * w1.x + xv.z * w2.x + xv.w * w3.x;
                acc[j].y += xv.x * w0.y + xv.y * w1.y + xv.z * w2.y + xv.w * w3.y;
                acc[j].z += xv.x * w0.z + xv.y * w1.z + xv.z * w2.z + xv.w * w3.z;
                acc[j].w += xv.x * w0.w + xv.y * w1.w + xv.z * w2.w + xv.w * w3.w;
            }
        }
    }
    #pragma unroll
    for (int j = 0; j < 8; j++) {
        int node = node0 + ng * 8 + j;
        if (node < NN) {
            float4 o;
            o.x = lrelu(acc[j].x, 0.01f);
            o.y = lrelu(acc[j].y, 0.01f);
            o.z = lrelu(acc[j].z, 0.01f);
            o.w = lrelu(acc[j].w, 0.01f);
            ((float4*)d_x)[node * 16 + f4] = o;
        }
    }
}

// ---------------- per-layer linear: g = norm(x) @ W + b ----------------------
__global__ void __launch_bounds__(256, 3) k_lin(const float* __restrict__ w,
                                                const float* __restrict__ b,
                                                int donorm, int hmode) {
    __shared__ float Wsm[F * F];         // 16 KB, row-major [k][f]
    __shared__ float Xin[128 * F];       // 32 KB
    int tid = threadIdx.x;
    {
        const float4* wg = (const float4*)w;
        float4* ws = (float4*)Wsm;
        #pragma unroll
        for (int q = tid; q < F * F / 4; q += 256) ws[q] = wg[q];
    }
    int node0 = blockIdx.x * 128;
    {
        float4* xs = (float4*)Xin;
        const float4* xg = (const float4*)d_x;
        float4* hg = (float4*)d_h;
        for (int q = tid; q < 128 * 16; q += 256) {
            int node = node0 + (q >> 4);
            float4 xv = make_float4(0.f, 0.f, 0.f, 0.f);
            if (node < NN) {
                xv = xg[node0 * 16 + q];
                if (donorm) {
                    int fi = q & 15;
                    float4 sc = ((const float4*)d_scale)[fi];
                    float4 sh = ((const float4*)d_shift)[fi];
                    xv.x = lrelu(xv.x * sc.x + sh.x, 0.01f);
                    xv.y = lrelu(xv.y * sc.y + sh.y, 0.01f);
                    xv.z = lrelu(xv.z * sc.z + sh.z, 0.01f);
                    xv.w = lrelu(xv.w * sc.w + sh.w, 0.01f);
                    float4 hv;
                    if (hmode == 1) {
                        hv = make_float4(0.5f * xv.x, 0.5f * xv.y,
                                         0.5f * xv.z, 0.5f * xv.w);
                    } else {
                        hv = hg[node0 * 16 + q];
                        hv.x += 0.5f * xv.x; hv.y += 0.5f * xv.y;
                        hv.z += 0.5f * xv.z; hv.w += 0.5f * xv.w;
                    }
                    hg[node0 * 16 + q] = hv;
                }
            }
            xs[q] = xv;
        }
    }
    __syncthreads();
    int f4 = tid & 15;
    int ng = tid >> 4;
    const float4* W4 = (const float4*)Wsm;
    const float4* X4 = (const float4*)(&Xin[ng * 8 * F]);
    float4 bb = ((const float4*)b)[f4];
    float4 acc[8];
    #pragma unroll
    for (int j = 0; j < 8; j++) acc[j] = bb;
    #pragma unroll 2
    for (int k4 = 0; k4 < F / 4; k4++) {
        float4 w0 = W4[(4 * k4 + 0) * 16 + f4];
        float4 w1 = W4[(4 * k4 + 1) * 16 + f4];
        float4 w2 = W4[(4 * k4 + 2) * 16 + f4];
        float4 w3 = W4[(4 * k4 + 3) * 16 + f4];
        #pragma unroll
        for (int j = 0; j < 8; j++) {
            float4 xv = X4[j * (F / 4) + k4];
            acc[j].x += xv.x * w0.x + xv.y * w1.x + xv.z * w2.x + xv.w * w3.x;
            acc[j].y += xv.x * w0.y + xv.y * w1.y + xv.z * w2.y + xv.w * w3.y;
            acc[j].z += xv.x * w0.z + xv.y * w1.z + xv.z * w2.z + xv.w * w3.z;
            acc[j].w += xv.x * w0.w + xv.y * w1.w + xv.z * w2.w + xv.w * w3.w;
        }
    }
    #pragma unroll
    for (int j = 0; j < 8; j++) {
        int node = node0 + ng * 8 + j;
        if (node < NN)
            ((float4*)d_g)[node * 16 + f4] = acc[j];
    }
}

// 8-feature logit contribution for one lane
#define DOT8(va, vb)                                                          \
    (lrelu((va).x + gda.x, 0.2f) * aa.x + lrelu((va).y + gda.y, 0.2f) * aa.y  \
   + lrelu((va).z + gda.z, 0.2f) * aa.z + lrelu((va).w + gda.w, 0.2f) * aa.w  \
   + lrelu((vb).x + gdb.x, 0.2f) * ab.x + lrelu((vb).y + gdb.y, 0.2f) * ab.y  \
   + lrelu((vb).z + gdb.z, 0.2f) * ab.z + lrelu((vb).w + gdb.w, 0.2f) * ab.w)

// branchless online-softmax update (8-feature acc), single MUFU
#define OUPD8(t, va, vb)                                            \
    {                                                               \
        bool gt = (t) > m;                                          \
        float es = __expf(-fabsf((t) - m));                         \
        float cs = gt ? es : 1.f;                                   \
        float ee = gt ? 1.f : es;                                   \
        ssum = ssum * cs + ee;                                      \
        accA.x = accA.x * cs + ee * (va).x;                         \
        accA.y = accA.y * cs + ee * (va).y;                         \
        accA.z = accA.z * cs + ee * (va).z;                         \
        accA.w = accA.w * cs + ee * (va).w;                         \
        accB.x = accB.x * cs + ee * (vb).x;                         \
        accB.y = accB.y * cs + ee * (vb).y;                         \
        accB.z = accB.z * cs + ee * (vb).z;                         \
        accB.w = accB.w * cs + ee * (vb).w;                         \
        m = fmaxf(m, (t));                                          \
    }

// ---------------- fused GATv2 edge phase + GraphNorm partial reduction --------
// One warp per dst node; QUARTER-WARP (8 lanes) per edge, lane holds 8 features.
// 8 edges per iteration via 2 interleaved 3-level shfl chains.
// launch_bounds(256,4): cap regs at 64 -> 32 warps/SM for max latency hiding.
__global__ void __launch_bounds__(256, 4) k_gat(const float* __restrict__ att,
                                                const float* __restrict__ cb,
                                                float* __restrict__ xs_out) {
    __shared__ float sm_s[8 * F];   // [warp][feature] x sums
    __shared__ float sm_q[8 * F];   // [warp][feature] x^2 sums
    int w = (blockIdx.x * blockDim.x + threadIdx.x) >> 5;
    int lane = threadIdx.x & 31;
    int wl = threadIdx.x >> 5;      // warp index in block
    // grid is exactly NN/8 blocks (NN % 8 == 0): every warp owns a valid node.
    int beg = d_off[w], end = d_off[w + 1];
    int qt = lane >> 3;         // quarter: 0..3
    int r  = lane & 7;          // float4 slot within half-row

    const float4* g4 = (const float4*)d_g;
    float4 aa  = __ldg((const float4*)att + r);
    float4 ab  = __ldg((const float4*)att + 8 + r);
    float4 gda = __ldg(g4 + w * 16 + r);
    float4 gdb = __ldg(g4 + w * 16 + 8 + r);

    float m = -1e30f, ssum = 0.f;
    float4 accA = make_float4(0.f, 0.f, 0.f, 0.f);
    float4 accB = make_float4(0.f, 0.f, 0.f, 0.f);

    int p = beg;
    for (; p + 7 < end; p += 8) {
        int s0 = __ldg(d_ssrc + p + qt);          // chain0: edges p..p+3
        int s1 = __ldg(d_ssrc + p + 4 + qt);      // chain1: edges p+4..p+7
        float4 va0 = __ldg(g4 + s0 * 16 + r);
        float4 vb0 = __ldg(g4 + s0 * 16 + 8 + r);
        float4 va1 = __ldg(g4 + s1 * 16 + r);
        float4 vb1 = __ldg(g4 + s1 * 16 + 8 + r);
        float t0 = DOT8(va0, vb0);
        float t1 = DOT8(va1, vb1);
        #pragma unroll
        for (int o = 4; o > 0; o >>= 1) {         // reduce within 8-lane quarter
            t0 += __shfl_xor_sync(0xFFFFFFFFu, t0, o);
            t1 += __shfl_xor_sync(0xFFFFFFFFu, t1, o);
        }
        if (r == 0) { d_e[p + qt] = t0; d_e[p + 4 + qt] = t1; }
        OUPD8(t0, va0, vb0);
        OUPD8(t1, va1, vb1);
    }
    // remainder: clamped groups of 4 edges (phantoms neutralized with -inf)
    for (; p < end; p += 4) {
        int idx = p + qt;
        bool valid = idx < end;
        if (!valid) idx = end - 1;
        int s0 = __ldg(d_ssrc + idx);
        float4 va = __ldg(g4 + s0 * 16 + r);
        float4 vb = __ldg(g4 + s0 * 16 + 8 + r);
        float t0 = DOT8(va, vb);
        #pragma unroll
        for (int o = 4; o > 0; o >>= 1)
            t0 += __shfl_xor_sync(0xFFFFFFFFu, t0, o);
        if (!valid) t0 = -CUDART_INF_F;
        if (r == 0 && valid) d_e[idx] = t0;
        OUPD8(t0, va, vb);
    }

    // merge the 4 quarter-states
    #pragma unroll
    for (int off = 16; off >= 8; off >>= 1) {
        float mO = __shfl_down_sync(0xFFFFFFFFu, m, off);
        float sO = __shfl_down_sync(0xFFFFFFFFu, ssum, off);
        float4 aO, bO;
        aO.x = __shfl_down_sync(0xFFFFFFFFu, accA.x, off);
        aO.y = __shfl_down_sync(0xFFFFFFFFu, accA.y, off);
        aO.z = __shfl_down_sync(0xFFFFFFFFu, accA.z, off);
        aO.w = __shfl_down_sync(0xFFFFFFFFu, accA.w, off);
        bO.x = __shfl_down_sync(0xFFFFFFFFu, accB.x, off);
        bO.y = __shfl_down_sync(0xFFFFFFFFu, accB.y, off);
        bO.z = __shfl_down_sync(0xFFFFFFFFu, accB.z, off);
        bO.w = __shfl_down_sync(0xFFFFFFFFu, accB.w, off);
        float M2 = fmaxf(m, mO);
        float cA = __expf(m - M2), cB = __expf(mO - M2);
        ssum  = ssum * cA + sO * cB;
        accA.x = accA.x * cA + aO.x * cB;
        accA.y = accA.y * cA + aO.y * cB;
        accA.z = accA.z * cA + aO.z * cB;
        accA.w = accA.w * cA + aO.w * cB;
        accB.x = accB.x * cA + bO.x * cB;
        accB.y = accB.y * cA + bO.y * cB;
        accB.z = accB.z * cA + bO.z * cB;
        accB.w = accB.w * cA + bO.w * cB;
        m = M2;
    }
    float inv = 1.f / ssum;
    float M = __shfl_sync(0xFFFFFFFFu, m, lane & 7);
    inv     = __shfl_sync(0xFFFFFFFFu, inv, lane & 7);

    // alpha pass: scalar logit -> alpha, lanes stride over edges
    for (int e = beg + lane; e < end; e += 32)
        xs_out[d_seid[e]] = __expf(d_e[e] - M) * inv;

    if (lane < 8) {
        float4 cba = __ldg((const float4*)cb + r);
        float4 cbb = __ldg((const float4*)cb + 8 + r);
        float4 xa, xb;
        xa.x = accA.x * inv + cba.x;
        xa.y = accA.y * inv + cba.y;
        xa.z = accA.z * inv + cba.z;
        xa.w = accA.w * inv + cba.w;
        xb.x = accB.x * inv + cbb.x;
        xb.y = accB.y * inv + cbb.y;
        xb.z = accB.z * inv + cbb.z;
        xb.w = accB.w * inv + cbb.w;
        ((float4*)d_x)[w * 16 + r]     = xa;
        ((float4*)d_x)[w * 16 + 8 + r] = xb;
        // stash for block GraphNorm reduction
        float* ss = &sm_s[wl * F];
        float* sq = &sm_q[wl * F];
        ss[4 * r + 0] = xa.x;  sq[4 * r + 0] = xa.x * xa.x;
        ss[4 * r + 1] = xa.y;  sq[4 * r + 1] = xa.y * xa.y;
        ss[4 * r + 2] = xa.z;  sq[4 * r + 2] = xa.z * xa.z;
        ss[4 * r + 3] = xa.w;  sq[4 * r + 3] = xa.w * xa.w;
        ss[32 + 4 * r + 0] = xb.x;  sq[32 + 4 * r + 0] = xb.x * xb.x;
        ss[32 + 4 * r + 1] = xb.y;  sq[32 + 4 * r + 1] = xb.y * xb.y;
        ss[32 + 4 * r + 2] = xb.z;  sq[32 + 4 * r + 2] = xb.z * xb.z;
        ss[32 + 4 * r + 3] = xb.w;  sq[32 + 4 * r + 3] = xb.w * xb.w;
    }
    __syncthreads();
    if (threadIdx.x < F) {
        int f = threadIdx.x;
        float s = 0.f, s2 = 0.f;
        #pragma unroll
        for (int k = 0; k < 8; k++) {
            s  += sm_s[k * F + f];
            s2 += sm_q[k * F + f];
        }
        atomicAdd(&d_sum[f], s);
        atomicAdd(&d_sumsq[f], s2);
    }
}

// stats: compute scale/shift, then zero accumulators for next layer/replay
__global__ void k_stats(const float* __restrict__ gw, const float* __restrict__ gb,
                        const float* __restrict__ gms) {
    int f = threadIdx.x;
    if (f >= F) return;
    const float invn = 1.f / (float)NN;
    float mean = d_sum[f] * invn;
    float ex2  = d_sumsq[f] * invn;
    float mm   = mean * gms[f];
    float var  = ex2 - 2.f * mm * mean + mm * mm;
    float inv  = rsqrtf(var + 1e-5f);
    float sc   = inv * gw[f];
    d_scale[f] = sc;
    d_shift[f] = gb[f] - mm * sc;
    d_sum[f] = 0.f;
    d_sumsq[f] = 0.f;
}

// final norm: apply last layer's GraphNorm, write outputs x and h
__global__ void k_norm_final(float* __restrict__ outx, float* __restrict__ outh) {
    int total = NN * F;
    for (int i = blockIdx.x * blockDim.x + threadIdx.x; i < total;
         i += gridDim.x * blockDim.x) {
        int f = i & 63;
        float v = d_x[i] * d_scale[f] + d_shift[f];
        v = lrelu(v, 0.01f);
        outx[i] = v;
        outh[i] = d_h[i] + 0.5f * v;
    }
}

// ---------------- launch ------------------------------------------------------
extern "C" void kernel_launch(void* const* d_in, const int* in_sizes, int n_in,
                              void* d_out, int out_size) {
    const float* x_feat   = (const float*)d_in[0];
    const int*   node_ids = (const int*)  d_in[1];
    const int*   edge_idx = (const int*)  d_in[2];
    const float* emb      = (const float*)d_in[3];
    const float* w_in     = (const float*)d_in[4];
    const float* b_in     = (const float*)d_in[5];
    const float* lin_w    = (const float*)d_in[6];
    const float* lin_b    = (const float*)d_in[7];
    const float* att      = (const float*)d_in[8];
    const float* conv_b   = (const float*)d_in[9];
    const float* gn_w     = (const float*)d_in[10];
    const float* gn_b     = (const float*)d_in[11];
    const float* gn_ms    = (const float*)d_in[12];
    float* out = (float*)d_out;

    k_enc<<<(NN + 127) / 128, 256>>>(x_feat, node_ids, emb, w_in, b_in);
    k_hist<<<(NE + 255) / 256, 256>>>(edge_idx);
    k_scan1<<<NSB, SCAN_B>>>();
    k_lin<<<(NN + 127) / 128, 256>>>(lin_w, lin_b, 0, 0);   // layer 0, no norm
    k_scan2<<<1, 128>>>();
    k_scan3<<<NSB, SCAN_B>>>();
    k_scatter<<<(ET + 255) / 256, 256>>>(edge_idx);

    for (int l = 0; l < NLAY; l++) {
        if (l > 0)   // layers 1-3: fused norm of previous layer + h accumulate
            k_lin<<<(NN + 127) / 128, 256>>>(lin_w + l * F * F, lin_b + l * F,
                                             1, l == 1 ? 1 : 2);
        k_gat<<<NN / 8, 256>>>(att + l * F, conv_b + l * F,
                               out + 2 * NN * F + (size_t)l * ET);
        k_stats<<<1, 64>>>(gn_w + l * F, gn_b + l * F, gn_ms + l * F);
    }

    k_norm_final<<<1024, 256>>>(out, out + NN * F);

    (void)in_sizes; (void)n_in; (void)out_size;
}